// round 2
// baseline (speedup 1.0000x reference)
#include <cuda_runtime.h>

// GAE backward scan.
// Inputs (metadata order): reward, terminated, value, next_value -- all (8192,256,4,1) fp32.
// Output: [advantages | returns] concatenated, each 8192*256*4 fp32.
//
// delta_t  = r_t + GAMMA * nv_t * nd_t - v_t
// gae_t    = delta_t + GAMMA*LMBDA * nd_t * gae_{t+1}   (gae_T = 0, backward)
// adv_t    = gae_t ; ret_t = gae_t + v_t

#define GAMMA  0.99f
#define LMBDA  0.95f

#define B_TOT  8192
#define T_TOT  256
#define A_TOT  4

#define BB     32          // batches per block
#define TC     64          // timesteps per chunk
#define ROWF4  (TC + 1)    // padded row stride in float4 (bank-conflict-free scan)
#define NTHREADS 128       // one thread per (b_local, agent)

// dynamic smem layout: three arrays of BB*ROWF4 float4 each
#define ARR_F4 (BB * ROWF4)

__global__ __launch_bounds__(NTHREADS, 2)
void gae_kernel(const float4* __restrict__ reward,
                const float4* __restrict__ terminated,
                const float4* __restrict__ value,
                const float4* __restrict__ next_value,
                float4* __restrict__ adv_out,
                float4* __restrict__ ret_out)
{
    extern __shared__ float4 smem[];
    float4* s_delta = smem;                // [BB][ROWF4] : delta, then adv in-place
    float4* s_ndgl  = smem + ARR_F4;       // gamma*lambda*not_done
    float4* s_val   = smem + 2 * ARR_F4;   // value, then ret in-place

    const int tid = threadIdx.x;
    const int b0  = blockIdx.x * BB;

    // scan-thread mapping: one thread per (b_local, agent)
    const int bl = tid >> 2;
    const int a  = tid & 3;
    float* s_delta_f = reinterpret_cast<float*>(s_delta);
    float* s_ndgl_f  = reinterpret_cast<float*>(s_ndgl);
    float* s_val_f   = reinterpret_cast<float*>(s_val);

    float gae = 0.0f;   // carries across chunks (backward in time)

    // backward over T in chunks of TC
    for (int t0 = T_TOT - TC; t0 >= 0; t0 -= TC) {

        // ---- coalesced load + elementwise delta ----
        // each float4 = one (b, t) across 4 agents; per-b segment of TC float4s
        // is contiguous in global memory.
        #pragma unroll
        for (int i = tid; i < BB * TC; i += NTHREADS) {
            const int lbl = i >> 6;          // i / TC   (TC == 64)
            const int tr  = i & (TC - 1);    // i % TC
            const long g  = (long)(b0 + lbl) * T_TOT + (t0 + tr);

            const float4 r  = reward[g];
            const float4 tm = terminated[g];
            const float4 v  = value[g];
            const float4 nv = next_value[g];

            float4 nd, d, m;
            nd.x = 1.0f - tm.x; nd.y = 1.0f - tm.y;
            nd.z = 1.0f - tm.z; nd.w = 1.0f - tm.w;

            d.x = r.x + GAMMA * nv.x * nd.x - v.x;
            d.y = r.y + GAMMA * nv.y * nd.y - v.y;
            d.z = r.z + GAMMA * nv.z * nd.z - v.z;
            d.w = r.w + GAMMA * nv.w * nd.w - v.w;

            const float gl = GAMMA * LMBDA;
            m.x = gl * nd.x; m.y = gl * nd.y; m.z = gl * nd.z; m.w = gl * nd.w;

            const int s = lbl * ROWF4 + tr;
            s_delta[s] = d;
            s_ndgl[s]  = m;
            s_val[s]   = v;
        }
        __syncthreads();

        // ---- backward scan within chunk (bank-conflict-free) ----
        #pragma unroll 8
        for (int t = TC - 1; t >= 0; --t) {
            const int idx = (bl * ROWF4 + t) * 4 + a;
            const float d = s_delta_f[idx];
            const float m = s_ndgl_f[idx];
            gae = fmaf(m, gae, d);
            s_delta_f[idx] = gae;                    // advantage in place
            s_val_f[idx]   = gae + s_val_f[idx];     // return in place
        }
        __syncthreads();

        // ---- coalesced store ----
        #pragma unroll
        for (int i = tid; i < BB * TC; i += NTHREADS) {
            const int lbl = i >> 6;
            const int tr  = i & (TC - 1);
            const long g  = (long)(b0 + lbl) * T_TOT + (t0 + tr);
            const int s   = lbl * ROWF4 + tr;
            adv_out[g] = s_delta[s];
            ret_out[g] = s_val[s];
        }
        __syncthreads();   // protect shared before next chunk's load overwrites
    }
}

extern "C" void kernel_launch(void* const* d_in, const int* in_sizes, int n_in,
                              void* d_out, int out_size)
{
    const float4* reward     = (const float4*)d_in[0];
    const float4* terminated = (const float4*)d_in[1];
    const float4* value      = (const float4*)d_in[2];
    const float4* next_value = (const float4*)d_in[3];

    const int n_elems = B_TOT * T_TOT * A_TOT;   // 8388608 per tensor
    float4* adv_out = (float4*)d_out;
    float4* ret_out = (float4*)((float*)d_out + n_elems);

    const size_t smem_bytes = 3 * ARR_F4 * sizeof(float4);   // 99840 B
    cudaFuncSetAttribute(gae_kernel,
                         cudaFuncAttributeMaxDynamicSharedMemorySize,
                         (int)smem_bytes);

    dim3 grid(B_TOT / BB);      // 256 blocks
    dim3 block(NTHREADS);       // 128 threads
    gae_kernel<<<grid, block, smem_bytes>>>(reward, terminated, value, next_value,
                                            adv_out, ret_out);
}